// round 1
// baseline (speedup 1.0000x reference)
#include <cuda_runtime.h>
#include <math.h>

#define NN 4096
#define TT 4
#define DD 128
#define NT (NN*TT)           // 16384 rows
#define TILE_J 128
#define NTILES (NN/TILE_J)   // 32

// ---------------- scratch (device globals; no allocations) ----------------
__device__ float g_Wx[TT*NN*DD];        // Wx in [t][n][d] layout, 8 MB
__device__ float g_u[TT*NN];            // Wx·a1/16  (softmax-axis scores)
__device__ float g_c[TT*NN];            // Wx·a2/16  (per-query shifts)
__device__ float g_us[TT*NN];           // sorted u per t
__device__ int   g_perm[TT*NN];         // sort permutation
__device__ float g_tileE[TT*NTILES*DD];
__device__ float g_tileF[TT*NTILES*DD];
__device__ float g_tileE1[TT*NTILES];
__device__ float g_tileF1[TT*NTILES];
__device__ float g_offE[TT*NTILES*DD];
__device__ float g_offF[TT*NTILES*DD];
__device__ float g_offE1[TT*NTILES];
__device__ float g_offF1[TT*NTILES];
__device__ float g_preE[TT*(NN+1)*DD];  // exclusive prefix of e^{u_j}·V_j  (sorted order)
__device__ float g_preF[TT*(NN+1)*DD];  // exclusive prefix of e^{0.01u_j}·V_j
__device__ float g_preE1[TT*(NN+1)];    // scalar prefixes
__device__ float g_preF1[TT*(NN+1)];

// ---------------- K1: Wx = x @ W, written transposed to [t][n][d] ----------
// 128x128 tile per block, 256 threads, 8x8 microtile, Ktile=32.
__global__ void k_gemm(const float* __restrict__ x, const float* __restrict__ W) {
    __shared__ float Xs[32][132];   // [k][m], padded for alignment/banks
    __shared__ float Ws[32][128];   // [k][j]
    const int tid = threadIdx.x;
    const int tx = tid & 15, ty = tid >> 4;
    const int row0 = blockIdx.x * 128;

    float acc[8][8];
#pragma unroll
    for (int i = 0; i < 8; i++)
#pragma unroll
        for (int j = 0; j < 8; j++) acc[i][j] = 0.0f;

    for (int k0 = 0; k0 < DD; k0 += 32) {
        // load X tile (128 rows x 32 k), store transposed [k][m]
#pragma unroll
        for (int q = 0; q < 4; q++) {
            int m  = (tid >> 3) + q * 32;
            int kq = (tid & 7) * 4;
            float4 v = *(const float4*)(x + (size_t)(row0 + m) * DD + k0 + kq);
            Xs[kq + 0][m] = v.x; Xs[kq + 1][m] = v.y;
            Xs[kq + 2][m] = v.z; Xs[kq + 3][m] = v.w;
        }
        // load W tile (32 k x 128 j)
#pragma unroll
        for (int q = 0; q < 4; q++) {
            int kk = (tid >> 5) + q * 8;
            int j4 = (tid & 31) * 4;
            *(float4*)&Ws[kk][j4] = *(const float4*)(W + (size_t)(k0 + kk) * DD + j4);
        }
        __syncthreads();
#pragma unroll
        for (int k = 0; k < 32; k++) {
            float a[8], b[8];
            float4 a0 = *(const float4*)&Xs[k][ty * 8];
            float4 a1v = *(const float4*)&Xs[k][ty * 8 + 4];
            a[0]=a0.x; a[1]=a0.y; a[2]=a0.z; a[3]=a0.w;
            a[4]=a1v.x; a[5]=a1v.y; a[6]=a1v.z; a[7]=a1v.w;
            float4 b0 = *(const float4*)&Ws[k][tx * 8];
            float4 b1v = *(const float4*)&Ws[k][tx * 8 + 4];
            b[0]=b0.x; b[1]=b0.y; b[2]=b0.z; b[3]=b0.w;
            b[4]=b1v.x; b[5]=b1v.y; b[6]=b1v.z; b[7]=b1v.w;
#pragma unroll
            for (int i = 0; i < 8; i++)
#pragma unroll
                for (int j = 0; j < 8; j++)
                    acc[i][j] += a[i] * b[j];
        }
        __syncthreads();
    }
    // store, remapping row r=n*T+t  ->  [t][n][d]
#pragma unroll
    for (int i = 0; i < 8; i++) {
        int r = row0 + ty * 8 + i;
        int t = r & 3;
        int n = r >> 2;
        float* o = g_Wx + ((size_t)(t * NN + n)) * DD + tx * 8;
        float4 v0 = make_float4(acc[i][0], acc[i][1], acc[i][2], acc[i][3]);
        float4 v1 = make_float4(acc[i][4], acc[i][5], acc[i][6], acc[i][7]);
        *(float4*)o = v0;
        *(float4*)(o + 4) = v1;
    }
}

// ---------------- K2: u = Wx·a1/16, c = Wx·a2/16 (warp per row) ------------
__global__ void k_uc(const float* __restrict__ a1, const float* __restrict__ a2) {
    int warp = (blockIdx.x * blockDim.x + threadIdx.x) >> 5;
    int lane = threadIdx.x & 31;
    if (warp >= NT) return;
    float4 v  = *(const float4*)(g_Wx + (size_t)warp * DD + lane * 4);
    float4 w1 = *(const float4*)(a1 + lane * 4);
    float4 w2 = *(const float4*)(a2 + lane * 4);
    float s1 = v.x * w1.x + v.y * w1.y + v.z * w1.z + v.w * w1.w;
    float s2 = v.x * w2.x + v.y * w2.y + v.z * w2.z + v.w * w2.w;
#pragma unroll
    for (int o = 16; o > 0; o >>= 1) {
        s1 += __shfl_xor_sync(0xFFFFFFFFu, s1, o);
        s2 += __shfl_xor_sync(0xFFFFFFFFu, s2, o);
    }
    if (lane == 0) {
        g_u[warp] = s1 * (1.0f / 16.0f);   // scale = sqrt(2*128) = 16 exactly
        g_c[warp] = s2 * (1.0f / 16.0f);
    }
}

// ---------------- K3: bitonic sort of u per t (block per t) ----------------
__global__ void k_sort() {
    __shared__ float sv[NN];
    __shared__ int   si[NN];
    const int t = blockIdx.x;
    for (int i = threadIdx.x; i < NN; i += blockDim.x) {
        sv[i] = g_u[t * NN + i];
        si[i] = i;
    }
    __syncthreads();
    for (int k = 2; k <= NN; k <<= 1) {
        for (int j = k >> 1; j > 0; j >>= 1) {
            for (int i = threadIdx.x; i < NN; i += blockDim.x) {
                int ixj = i ^ j;
                if (ixj > i) {
                    bool up = ((i & k) == 0);
                    float vi = sv[i], vj = sv[ixj];
                    if ((vi > vj) == up) {
                        sv[i] = vj; sv[ixj] = vi;
                        int tmp = si[i]; si[i] = si[ixj]; si[ixj] = tmp;
                    }
                }
            }
            __syncthreads();
        }
    }
    for (int i = threadIdx.x; i < NN; i += blockDim.x) {
        g_us[t * NN + i]   = sv[i];
        g_perm[t * NN + i] = si[i];
    }
}

// ---------------- K4a: per-tile sums of e^{u}·V and e^{0.01u}·V ------------
__global__ void k_tilesum() {
    const int t = blockIdx.y, tile = blockIdx.x, d = threadIdx.x;
    const int base = t * NN + tile * TILE_J;
    float sE = 0.f, sF = 0.f, sE1 = 0.f, sF1 = 0.f;
    for (int jj = 0; jj < TILE_J; jj++) {
        float us = g_us[base + jj];
        int   p  = g_perm[base + jj];
        float wE = expf(us);
        float wF = expf(0.01f * us);
        float v  = g_Wx[((size_t)(t * NN + p)) * DD + d];
        sE += wE * v; sF += wF * v; sE1 += wE; sF1 += wF;
    }
    int o = t * NTILES + tile;
    g_tileE[(size_t)o * DD + d] = sE;
    g_tileF[(size_t)o * DD + d] = sF;
    if (d == 0) { g_tileE1[o] = sE1; g_tileF1[o] = sF1; }
}

// ---------------- K4b: scan tile sums -> exclusive tile offsets ------------
__global__ void k_scan_tiles() {
    const int t = blockIdx.x, d = threadIdx.x;
    float rE = 0.f, rF = 0.f, rE1 = 0.f, rF1 = 0.f;
    for (int tile = 0; tile < NTILES; tile++) {
        int o = t * NTILES + tile;
        g_offE[(size_t)o * DD + d] = rE;
        g_offF[(size_t)o * DD + d] = rF;
        rE += g_tileE[(size_t)o * DD + d];
        rF += g_tileF[(size_t)o * DD + d];
        if (d == 0) {
            g_offE1[o] = rE1; g_offF1[o] = rF1;
            rE1 += g_tileE1[o]; rF1 += g_tileF1[o];
        }
    }
}

// ---------------- K4c: expand to full exclusive prefixes -------------------
__global__ void k_prefix() {
    const int t = blockIdx.y, tile = blockIdx.x, d = threadIdx.x;
    const int o = t * NTILES + tile;
    float rE = g_offE[(size_t)o * DD + d];
    float rF = g_offF[(size_t)o * DD + d];
    float rE1 = g_offE1[o], rF1 = g_offF1[o];
    const int base  = t * NN + tile * TILE_J;
    const int pbase = t * (NN + 1) + tile * TILE_J;
    for (int jj = 0; jj < TILE_J; jj++) {
        g_preE[(size_t)(pbase + jj) * DD + d] = rE;
        g_preF[(size_t)(pbase + jj) * DD + d] = rF;
        if (d == 0) { g_preE1[pbase + jj] = rE1; g_preF1[pbase + jj] = rF1; }
        float us = g_us[base + jj];
        int   p  = g_perm[base + jj];
        float wE = expf(us);
        float wF = expf(0.01f * us);
        float v  = g_Wx[((size_t)(t * NN + p)) * DD + d];
        rE += wE * v; rF += wF * v; rE1 += wE; rF1 += wF;
    }
    if (tile == NTILES - 1) {
        g_preE[(size_t)(t * (NN + 1) + NN) * DD + d] = rE;
        g_preF[(size_t)(t * (NN + 1) + NN) * DD + d] = rF;
        if (d == 0) { g_preE1[t * (NN + 1) + NN] = rE1; g_preF1[t * (NN + 1) + NN] = rF1; }
    }
}

// ---------------- K5: per (t,n): binary search + combine + residual --------
__global__ void k_out(const float* __restrict__ x, float* __restrict__ out) {
    int warp = (blockIdx.x * blockDim.x + threadIdx.x) >> 5;
    int lane = threadIdx.x & 31;
    if (warp >= NT) return;
    const int t = warp >> 12;        // / 4096
    const int n = warp & (NN - 1);
    const float c   = g_c[t * NN + n];
    const float thr = -c;
    const float* __restrict__ us = g_us + t * NN;
    // first index with us > thr  (== count of u_m <= -c, the negative-branch set)
    int lo = 0, hi = NN;
    while (lo < hi) {
        int mid = (lo + hi) >> 1;
        if (us[mid] <= thr) lo = mid + 1; else hi = mid;
    }
    const int k = lo;
    const float eC  = expf(c);
    const float eC2 = expf(0.01f * c);
    const int pb = t * (NN + 1);
    const float totE1 = g_preE1[pb + NN];
    const float denom = eC * (totE1 - g_preE1[pb + k]) + eC2 * g_preF1[pb + k];
    const float inv = 1.0f / denom;

    float4 pe = *(const float4*)(g_preE + (size_t)(pb + k)  * DD + lane * 4);
    float4 pf = *(const float4*)(g_preF + (size_t)(pb + k)  * DD + lane * 4);
    float4 te = *(const float4*)(g_preE + (size_t)(pb + NN) * DD + lane * 4);
    float4 xv = *(const float4*)(x + (size_t)(n * TT + t) * DD + lane * 4);

    float4 o;
    {
        float num, agg, l;
        num = eC * (te.x - pe.x) + eC2 * pf.x; agg = num * inv;
        l = (agg >= 0.f) ? agg : 0.01f * agg;  o.x = xv.x - l;
        num = eC * (te.y - pe.y) + eC2 * pf.y; agg = num * inv;
        l = (agg >= 0.f) ? agg : 0.01f * agg;  o.y = xv.y - l;
        num = eC * (te.z - pe.z) + eC2 * pf.z; agg = num * inv;
        l = (agg >= 0.f) ? agg : 0.01f * agg;  o.z = xv.z - l;
        num = eC * (te.w - pe.w) + eC2 * pf.w; agg = num * inv;
        l = (agg >= 0.f) ? agg : 0.01f * agg;  o.w = xv.w - l;
    }
    *(float4*)(out + (size_t)(n * TT + t) * DD + lane * 4) = o;
}

// ---------------------------------------------------------------------------
extern "C" void kernel_launch(void* const* d_in, const int* in_sizes, int n_in,
                              void* d_out, int out_size) {
    const float* x  = (const float*)d_in[0];
    const float* W  = (const float*)d_in[1];
    const float* a1 = (const float*)d_in[2];
    const float* a2 = (const float*)d_in[3];
    float* out = (float*)d_out;

    k_gemm<<<NT / 128, 256>>>(x, W);
    k_uc<<<NT / 8, 256>>>(a1, a2);
    k_sort<<<TT, 1024>>>();
    dim3 g4(NTILES, TT);
    k_tilesum<<<g4, DD>>>();
    k_scan_tiles<<<TT, DD>>>();
    k_prefix<<<g4, DD>>>();
    k_out<<<NT / 32, 1024>>>(x, out);
}

// round 3
// speedup vs baseline: 1.6361x; 1.6361x over previous
#include <cuda_runtime.h>
#include <math.h>

#define NN 4096
#define TT 4
#define DD 128
#define NT (NN*TT)           // 16384 rows
#define TILE_J 16
#define NTILES (NN/TILE_J)   // 256

// ---------------- scratch (device globals; no allocations) ----------------
__device__ float g_Wx[TT*NN*DD];        // Wx in [t][n][d] layout, 8 MB
__device__ float g_u[TT*NN];            // Wx·a1/16  (softmax-axis scores)
__device__ float g_c[TT*NN];            // Wx·a2/16  (per-query shifts)
__device__ float g_us[TT*NN];           // sorted u per t
__device__ int   g_perm[TT*NN];         // sort permutation
__device__ float g_wE[TT*NN];           // e^{us}
__device__ float g_wF[TT*NN];           // e^{0.01 us}
__device__ float g_tileE[TT*NTILES*DD]; // per-tile sums
__device__ float g_tileF[TT*NTILES*DD];
__device__ float g_tileE1[TT*NTILES];
__device__ float g_tileF1[TT*NTILES];
__device__ float g_offE[TT*NTILES*DD];  // exclusive tile offsets (L2-resident)
__device__ float g_offF[TT*NTILES*DD];
__device__ float g_offE1[TT*NTILES];
__device__ float g_offF1[TT*NTILES];
__device__ float g_totE[TT*DD];         // full-column totals
__device__ float g_totF[TT*DD];
__device__ float g_totE1[TT];
__device__ float g_totF1[TT];
__device__ float g_preE[TT*NN*DD];      // TILE-LOCAL exclusive prefixes (sorted order)
__device__ float g_preF[TT*NN*DD];
__device__ float g_preE1[TT*NN];
__device__ float g_preF1[TT*NN];

// ---------------- K1: Wx = x @ W (+ fused u,c epilogue) --------------------
// 128x128 tile per block, 256 threads, 8x8 microtile, Ktile=32.
__global__ void k_gemm(const float* __restrict__ x, const float* __restrict__ W,
                       const float* __restrict__ a1, const float* __restrict__ a2) {
    __shared__ float Xs[32][132];   // [k][m], padded
    __shared__ float Ws[32][128];   // [k][j]
    __shared__ float a1s[DD], a2s[DD];
    const int tid = threadIdx.x;
    const int tx = tid & 15, ty = tid >> 4;
    const int row0 = blockIdx.x * 128;

    if (tid < DD) { a1s[tid] = a1[tid]; a2s[tid] = a2[tid]; }

    float acc[8][8];
#pragma unroll
    for (int i = 0; i < 8; i++)
#pragma unroll
        for (int j = 0; j < 8; j++) acc[i][j] = 0.0f;

    for (int k0 = 0; k0 < DD; k0 += 32) {
#pragma unroll
        for (int q = 0; q < 4; q++) {
            int m  = (tid >> 3) + q * 32;
            int kq = (tid & 7) * 4;
            float4 v = *(const float4*)(x + (size_t)(row0 + m) * DD + k0 + kq);
            Xs[kq + 0][m] = v.x; Xs[kq + 1][m] = v.y;
            Xs[kq + 2][m] = v.z; Xs[kq + 3][m] = v.w;
        }
#pragma unroll
        for (int q = 0; q < 4; q++) {
            int kk = (tid >> 5) + q * 8;
            int j4 = (tid & 31) * 4;
            *(float4*)&Ws[kk][j4] = *(const float4*)(W + (size_t)(k0 + kk) * DD + j4);
        }
        __syncthreads();
#pragma unroll
        for (int k = 0; k < 32; k++) {
            float a[8], b[8];
            float4 a0 = *(const float4*)&Xs[k][ty * 8];
            float4 a1v = *(const float4*)&Xs[k][ty * 8 + 4];
            a[0]=a0.x; a[1]=a0.y; a[2]=a0.z; a[3]=a0.w;
            a[4]=a1v.x; a[5]=a1v.y; a[6]=a1v.z; a[7]=a1v.w;
            float4 b0 = *(const float4*)&Ws[k][tx * 8];
            float4 b1v = *(const float4*)&Ws[k][tx * 8 + 4];
            b[0]=b0.x; b[1]=b0.y; b[2]=b0.z; b[3]=b0.w;
            b[4]=b1v.x; b[5]=b1v.y; b[6]=b1v.z; b[7]=b1v.w;
#pragma unroll
            for (int i = 0; i < 8; i++)
#pragma unroll
                for (int j = 0; j < 8; j++)
                    acc[i][j] += a[i] * b[j];
        }
        __syncthreads();
    }
    // store Wx, remapping row r=n*T+t -> [t][n][d]; fused u,c reduction
#pragma unroll
    for (int i = 0; i < 8; i++) {
        int r = row0 + ty * 8 + i;
        int t = r & 3;
        int n = r >> 2;
        float* o = g_Wx + ((size_t)(t * NN + n)) * DD + tx * 8;
        *(float4*)o       = make_float4(acc[i][0], acc[i][1], acc[i][2], acc[i][3]);
        *(float4*)(o + 4) = make_float4(acc[i][4], acc[i][5], acc[i][6], acc[i][7]);

        float pu = 0.f, pc = 0.f;
#pragma unroll
        for (int j = 0; j < 8; j++) {
            pu += acc[i][j] * a1s[tx * 8 + j];
            pc += acc[i][j] * a2s[tx * 8 + j];
        }
#pragma unroll
        for (int off = 1; off <= 8; off <<= 1) {
            pu += __shfl_xor_sync(0xFFFFFFFFu, pu, off);
            pc += __shfl_xor_sync(0xFFFFFFFFu, pc, off);
        }
        if (tx == 0) {
            g_u[t * NN + n] = pu * (1.0f / 16.0f);  // scale = sqrt(2*128) = 16
            g_c[t * NN + n] = pc * (1.0f / 16.0f);
        }
    }
}

// ---------------- K2: packed u64 bitonic sort per t ------------------------
__global__ void k_sort() {
    __shared__ unsigned long long s[NN];
    const int t = blockIdx.x;
    for (int i = threadIdx.x; i < NN; i += blockDim.x) {
        unsigned int b = __float_as_uint(g_u[t * NN + i]);
        unsigned int m = (b & 0x80000000u) ? ~b : (b | 0x80000000u);
        s[i] = ((unsigned long long)m << 32) | (unsigned)i;
    }
    __syncthreads();
    for (int k = 2; k <= NN; k <<= 1) {
        for (int j = k >> 1; j > 0; j >>= 1) {
#pragma unroll 4
            for (int i = threadIdx.x; i < NN; i += 1024) {
                int ixj = i ^ j;
                if (ixj > i) {
                    bool up = ((i & k) == 0);
                    unsigned long long a = s[i], b = s[ixj];
                    if ((a > b) == up) { s[i] = b; s[ixj] = a; }
                }
            }
            __syncthreads();
        }
    }
    for (int i = threadIdx.x; i < NN; i += blockDim.x) {
        unsigned long long pk = s[i];
        unsigned int m = (unsigned int)(pk >> 32);
        unsigned int b = (m & 0x80000000u) ? (m & 0x7fffffffu) : ~m;
        float us = __uint_as_float(b);
        g_us[t * NN + i]   = us;
        g_perm[t * NN + i] = (int)(pk & 0xffffffffu);
        g_wE[t * NN + i]   = expf(us);
        g_wF[t * NN + i]   = expf(0.01f * us);
    }
}

// ---------------- K3: tile-local prefixes + tile totals (one Wx pass) ------
__global__ void k_prefix() {
    const int t = blockIdx.y, tile = blockIdx.x, d = threadIdx.x;
    const int base = t * NN + tile * TILE_J;
    float rE = 0.f, rF = 0.f, rE1 = 0.f, rF1 = 0.f;
#pragma unroll
    for (int jj = 0; jj < TILE_J; jj++) {
        const int row = base + jj;
        g_preE[(size_t)row * DD + d] = rE;
        g_preF[(size_t)row * DD + d] = rF;
        if (d == 0) { g_preE1[row] = rE1; g_preF1[row] = rF1; }
        float wE = g_wE[row];
        float wF = g_wF[row];
        int   p  = g_perm[row];
        float v  = g_Wx[((size_t)(t * NN + p)) * DD + d];
        rE += wE * v; rF += wF * v; rE1 += wE; rF1 += wF;
    }
    const int o = t * NTILES + tile;
    g_tileE[(size_t)o * DD + d] = rE;
    g_tileF[(size_t)o * DD + d] = rF;
    if (d == 0) { g_tileE1[o] = rE1; g_tileF1[o] = rF1; }
}

// ---------------- K4: warp-scan of tile totals -> exclusive offsets --------
__global__ void k_scan() {
    const unsigned FULL = 0xFFFFFFFFu;
    int gw   = (blockIdx.x * blockDim.x + threadIdx.x) >> 5;
    int lane = threadIdx.x & 31;
    if (gw < TT * DD) {
        int t = gw >> 7, d = gw & 127;
        float cE = 0.f, cF = 0.f;
#pragma unroll
        for (int ch = 0; ch < NTILES / 32; ch++) {
            int tile = ch * 32 + lane;
            size_t o = (size_t)(t * NTILES + tile) * DD + d;
            float vE = g_tileE[o], vF = g_tileF[o];
            float iE = vE, iF = vF;
#pragma unroll
            for (int off = 1; off < 32; off <<= 1) {
                float nE = __shfl_up_sync(FULL, iE, off);
                float nF = __shfl_up_sync(FULL, iF, off);
                if (lane >= off) { iE += nE; iF += nF; }
            }
            g_offE[o] = iE - vE + cE;
            g_offF[o] = iF - vF + cF;
            cE += __shfl_sync(FULL, iE, 31);
            cF += __shfl_sync(FULL, iF, 31);
        }
        g_totE[t * DD + d] = cE;
        g_totF[t * DD + d] = cF;
    } else if (gw < TT * DD + TT) {
        int t = gw - TT * DD;
        float cE = 0.f, cF = 0.f;
#pragma unroll
        for (int ch = 0; ch < NTILES / 32; ch++) {
            int tile = ch * 32 + lane;
            int o = t * NTILES + tile;
            float vE = g_tileE1[o], vF = g_tileF1[o];
            float iE = vE, iF = vF;
#pragma unroll
            for (int off = 1; off < 32; off <<= 1) {
                float nE = __shfl_up_sync(FULL, iE, off);
                float nF = __shfl_up_sync(FULL, iF, off);
                if (lane >= off) { iE += nE; iF += nF; }
            }
            g_offE1[o] = iE - vE + cE;
            g_offF1[o] = iF - vF + cF;
            cE += __shfl_sync(FULL, iE, 31);
            cF += __shfl_sync(FULL, iF, 31);
        }
        if (lane == 0) { g_totE1[t] = cE; g_totF1[t] = cF; }
    }
}

// ---------------- K5: per (t,n): binary search + combine + residual --------
__global__ void k_out(const float* __restrict__ x, float* __restrict__ out) {
    int warp = (blockIdx.x * blockDim.x + threadIdx.x) >> 5;
    int lane = threadIdx.x & 31;
    if (warp >= NT) return;
    const int t = warp >> 12;
    const int n = warp & (NN - 1);
    const float c   = g_c[t * NN + n];
    const float thr = -c;
    const float* __restrict__ us = g_us + t * NN;
    int lo = 0, hi = NN;                 // first index with us > thr
    while (lo < hi) {
        int mid = (lo + hi) >> 1;
        if (us[mid] <= thr) lo = mid + 1; else hi = mid;
    }
    const int k = lo;
    const float eC  = expf(c);
    const float eC2 = expf(0.01f * c);

    float4 te = *(const float4*)(g_totE + t * DD + lane * 4);
    float4 pe, pf;
    float pe1, pf1;
    if (k < NN) {
        const int tile = k >> 4;         // TILE_J = 16
        size_t ro = (size_t)(t * NN + k) * DD + lane * 4;
        size_t oo = (size_t)(t * NTILES + tile) * DD + lane * 4;
        float4 lE = *(const float4*)(g_preE + ro);
        float4 oE = *(const float4*)(g_offE + oo);
        float4 lF = *(const float4*)(g_preF + ro);
        float4 oF = *(const float4*)(g_offF + oo);
        pe = make_float4(lE.x + oE.x, lE.y + oE.y, lE.z + oE.z, lE.w + oE.w);
        pf = make_float4(lF.x + oF.x, lF.y + oF.y, lF.z + oF.z, lF.w + oF.w);
        pe1 = g_preE1[t * NN + k] + g_offE1[t * NTILES + tile];
        pf1 = g_preF1[t * NN + k] + g_offF1[t * NTILES + tile];
    } else {
        pe = te;
        pf = *(const float4*)(g_totF + t * DD + lane * 4);
        pe1 = g_totE1[t];
        pf1 = g_totF1[t];
    }
    const float denom = eC * (g_totE1[t] - pe1) + eC2 * pf1;
    const float inv = 1.0f / denom;

    float4 xv = *(const float4*)(x + (size_t)(n * TT + t) * DD + lane * 4);
    float4 o;
    {
        float num, agg, l;
        num = eC * (te.x - pe.x) + eC2 * pf.x; agg = num * inv;
        l = (agg >= 0.f) ? agg : 0.01f * agg;  o.x = xv.x - l;
        num = eC * (te.y - pe.y) + eC2 * pf.y; agg = num * inv;
        l = (agg >= 0.f) ? agg : 0.01f * agg;  o.y = xv.y - l;
        num = eC * (te.z - pe.z) + eC2 * pf.z; agg = num * inv;
        l = (agg >= 0.f) ? agg : 0.01f * agg;  o.z = xv.z - l;
        num = eC * (te.w - pe.w) + eC2 * pf.w; agg = num * inv;
        l = (agg >= 0.f) ? agg : 0.01f * agg;  o.w = xv.w - l;
    }
    *(float4*)(out + (size_t)(n * TT + t) * DD + lane * 4) = o;
}

// ---------------------------------------------------------------------------
extern "C" void kernel_launch(void* const* d_in, const int* in_sizes, int n_in,
                              void* d_out, int out_size) {
    const float* x  = (const float*)d_in[0];
    const float* W  = (const float*)d_in[1];
    const float* a1 = (const float*)d_in[2];
    const float* a2 = (const float*)d_in[3];
    float* out = (float*)d_out;

    k_gemm<<<NT / 128, 256>>>(x, W, a1, a2);
    k_sort<<<TT, 1024>>>();
    dim3 gp(NTILES, TT);
    k_prefix<<<gp, DD>>>();
    k_scan<<<65, 256>>>();
    k_out<<<NT / 32, 1024>>>(x, out);
}

// round 4
// speedup vs baseline: 1.7134x; 1.0472x over previous
#include <cuda_runtime.h>
#include <math.h>

#define NN 4096
#define TT 4
#define DD 128
#define NT (NN*TT)           // 16384 rows
#define TILE_J 16
#define NTILES (NN/TILE_J)   // 256

// ---------------- scratch (device globals; no allocations) ----------------
__device__ float g_Wx[TT*NN*DD];        // Wx in [t][n][d] layout, 8 MB
__device__ float g_u[TT*NN];
__device__ float g_c[TT*NN];
__device__ float g_us[TT*NN];           // sorted u per t
__device__ int   g_perm[TT*NN];
__device__ float g_wE[TT*NN];           // e^{us}
__device__ float g_wF[TT*NN];           // e^{0.01 us}
__device__ float g_tileE[TT*NTILES*DD];
__device__ float g_tileF[TT*NTILES*DD];
__device__ float g_tileE1[TT*NTILES];
__device__ float g_tileF1[TT*NTILES];
__device__ float g_offE[TT*NTILES*DD];
__device__ float g_offF[TT*NTILES*DD];
__device__ float g_offE1[TT*NTILES];
__device__ float g_offF1[TT*NTILES];
__device__ float g_totE[TT*DD];
__device__ float g_totF[TT*DD];
__device__ float g_totE1[TT];
__device__ float g_totF1[TT];
__device__ float g_preE[TT*NN*DD];      // TILE-LOCAL exclusive prefixes
__device__ float g_preF[TT*NN*DD];
__device__ float g_preE1[TT*NN];
__device__ float g_preF1[TT*NN];

// ---------------- f32x2 helpers (sm_100+) ----------------------------------
__device__ __forceinline__ unsigned long long pack2(float x, float y) {
    unsigned long long r;
    asm("mov.b64 %0, {%1, %2};" : "=l"(r) : "f"(x), "f"(y));
    return r;
}
__device__ __forceinline__ void unpack2(unsigned long long v, float& x, float& y) {
    asm("mov.b64 {%0, %1}, %2;" : "=f"(x), "=f"(y) : "l"(v));
}
__device__ __forceinline__ void ffma2(unsigned long long& acc,
                                      unsigned long long a, unsigned long long b) {
    asm("fma.rn.f32x2 %0, %1, %2, %0;" : "+l"(acc) : "l"(a), "l"(b));
}

// ---------------- K1: Wx = x @ W via f32x2 (+ fused u,c epilogue) ----------
__global__ void k_gemm(const float* __restrict__ x, const float* __restrict__ W,
                       const float* __restrict__ a1, const float* __restrict__ a2) {
    __shared__ float Xs[32][132];   // [k][m], padded
    __shared__ float Ws[32][128];   // [k][j]
    __shared__ float a1s[DD], a2s[DD];
    const int tid = threadIdx.x;
    const int tx = tid & 15, ty = tid >> 4;
    const int row0 = blockIdx.x * 128;

    if (tid < DD) { a1s[tid] = a1[tid]; a2s[tid] = a2[tid]; }

    unsigned long long accp[8][4];   // 8 rows x 4 packed col-pairs
#pragma unroll
    for (int i = 0; i < 8; i++)
#pragma unroll
        for (int jp = 0; jp < 4; jp++) accp[i][jp] = 0ull;

    for (int k0 = 0; k0 < DD; k0 += 32) {
#pragma unroll
        for (int q = 0; q < 4; q++) {
            int m  = (tid >> 3) + q * 32;
            int kq = (tid & 7) * 4;
            float4 v = *(const float4*)(x + (size_t)(row0 + m) * DD + k0 + kq);
            Xs[kq + 0][m] = v.x; Xs[kq + 1][m] = v.y;
            Xs[kq + 2][m] = v.z; Xs[kq + 3][m] = v.w;
        }
#pragma unroll
        for (int q = 0; q < 4; q++) {
            int kk = (tid >> 5) + q * 8;
            int j4 = (tid & 31) * 4;
            *(float4*)&Ws[kk][j4] = *(const float4*)(W + (size_t)(k0 + kk) * DD + j4);
        }
        __syncthreads();
#pragma unroll
        for (int k = 0; k < 32; k++) {
            float a[8];
            float4 a0  = *(const float4*)&Xs[k][ty * 8];
            float4 a1v = *(const float4*)&Xs[k][ty * 8 + 4];
            a[0]=a0.x; a[1]=a0.y; a[2]=a0.z; a[3]=a0.w;
            a[4]=a1v.x; a[5]=a1v.y; a[6]=a1v.z; a[7]=a1v.w;
            unsigned long long b[4];
#pragma unroll
            for (int jp = 0; jp < 4; jp++)
                b[jp] = *(const unsigned long long*)&Ws[k][tx * 8 + jp * 2];
#pragma unroll
            for (int i = 0; i < 8; i++) {
                unsigned long long aa = pack2(a[i], a[i]);
#pragma unroll
                for (int jp = 0; jp < 4; jp++)
                    ffma2(accp[i][jp], aa, b[jp]);
            }
        }
        __syncthreads();
    }
    // store Wx (remap r=n*T+t -> [t][n][d]); fused u,c reduction
#pragma unroll
    for (int i = 0; i < 8; i++) {
        float acc[8];
#pragma unroll
        for (int jp = 0; jp < 4; jp++)
            unpack2(accp[i][jp], acc[jp * 2], acc[jp * 2 + 1]);

        int r = row0 + ty * 8 + i;
        int t = r & 3;
        int n = r >> 2;
        float* o = g_Wx + ((size_t)(t * NN + n)) * DD + tx * 8;
        *(float4*)o       = make_float4(acc[0], acc[1], acc[2], acc[3]);
        *(float4*)(o + 4) = make_float4(acc[4], acc[5], acc[6], acc[7]);

        float pu = 0.f, pc = 0.f;
#pragma unroll
        for (int j = 0; j < 8; j++) {
            pu += acc[j] * a1s[tx * 8 + j];
            pc += acc[j] * a2s[tx * 8 + j];
        }
#pragma unroll
        for (int off = 1; off <= 8; off <<= 1) {
            pu += __shfl_xor_sync(0xFFFFFFFFu, pu, off);
            pc += __shfl_xor_sync(0xFFFFFFFFu, pc, off);
        }
        if (tx == 0) {
            g_u[t * NN + n] = pu * (1.0f / 16.0f);   // scale = sqrt(2*128)=16
            g_c[t * NN + n] = pc * (1.0f / 16.0f);
        }
    }
}

// ---------------- K2: packed u64 bitonic sort per t ------------------------
__global__ void k_sort() {
    __shared__ unsigned long long s[NN];
    const int t = blockIdx.x;
    for (int i = threadIdx.x; i < NN; i += blockDim.x) {
        unsigned int b = __float_as_uint(g_u[t * NN + i]);
        unsigned int m = (b & 0x80000000u) ? ~b : (b | 0x80000000u);
        s[i] = ((unsigned long long)m << 32) | (unsigned)i;
    }
    __syncthreads();
    for (int k = 2; k <= NN; k <<= 1) {
        for (int j = k >> 1; j > 0; j >>= 1) {
#pragma unroll 4
            for (int i = threadIdx.x; i < NN; i += 1024) {
                int ixj = i ^ j;
                if (ixj > i) {
                    bool up = ((i & k) == 0);
                    unsigned long long a = s[i], b = s[ixj];
                    if ((a > b) == up) { s[i] = b; s[ixj] = a; }
                }
            }
            __syncthreads();
        }
    }
    for (int i = threadIdx.x; i < NN; i += blockDim.x) {
        unsigned long long pk = s[i];
        unsigned int m = (unsigned int)(pk >> 32);
        unsigned int b = (m & 0x80000000u) ? (m & 0x7fffffffu) : ~m;
        float us = __uint_as_float(b);
        g_us[t * NN + i]   = us;
        g_perm[t * NN + i] = (int)(pk & 0xffffffffu);
        g_wE[t * NN + i]   = expf(us);
        g_wF[t * NN + i]   = expf(0.01f * us);
    }
}

// ---------------- K3: tile-local prefixes + tile totals (one Wx pass) ------
__global__ void k_prefix() {
    const int t = blockIdx.y, tile = blockIdx.x, d = threadIdx.x;
    const int base = t * NN + tile * TILE_J;
    float rE = 0.f, rF = 0.f, rE1 = 0.f, rF1 = 0.f;
#pragma unroll
    for (int jj = 0; jj < TILE_J; jj++) {
        const int row = base + jj;
        g_preE[(size_t)row * DD + d] = rE;
        g_preF[(size_t)row * DD + d] = rF;
        if (d == 0) { g_preE1[row] = rE1; g_preF1[row] = rF1; }
        float wE = g_wE[row];
        float wF = g_wF[row];
        int   p  = g_perm[row];
        float v  = g_Wx[((size_t)(t * NN + p)) * DD + d];
        rE += wE * v; rF += wF * v; rE1 += wE; rF1 += wF;
    }
    const int o = t * NTILES + tile;
    g_tileE[(size_t)o * DD + d] = rE;
    g_tileF[(size_t)o * DD + d] = rF;
    if (d == 0) { g_tileE1[o] = rE1; g_tileF1[o] = rF1; }
}

// ---------------- K4: block-parallel scan of tile totals -------------------
// grid (DD+1, TT), 256 threads; thread == tile. blockIdx.x==DD does scalars.
__global__ void k_scan() {
    __shared__ float wsE[8], wsF[8];
    const unsigned FULL = 0xFFFFFFFFu;
    const int t = blockIdx.y;
    const int tile = threadIdx.x;
    const int lane = tile & 31, w = tile >> 5;

    float vE, vF;
    size_t o;
    if (blockIdx.x < DD) {
        const int d = blockIdx.x;
        o = (size_t)(t * NTILES + tile) * DD + d;
        vE = g_tileE[o]; vF = g_tileF[o];
    } else {
        o = (size_t)(t * NTILES + tile);
        vE = g_tileE1[o]; vF = g_tileF1[o];
    }
    float iE = vE, iF = vF;
#pragma unroll
    for (int off = 1; off < 32; off <<= 1) {
        float nE = __shfl_up_sync(FULL, iE, off);
        float nF = __shfl_up_sync(FULL, iF, off);
        if (lane >= off) { iE += nE; iF += nF; }
    }
    if (lane == 31) { wsE[w] = iE; wsF[w] = iF; }
    __syncthreads();
    float oE = 0.f, oF = 0.f;
#pragma unroll
    for (int q = 0; q < 8; q++) {
        if (q < w) { oE += wsE[q]; oF += wsF[q]; }
    }
    if (blockIdx.x < DD) {
        g_offE[o] = iE - vE + oE;
        g_offF[o] = iF - vF + oF;
        if (tile == NTILES - 1) {
            g_totE[t * DD + blockIdx.x] = iE + oE;
            g_totF[t * DD + blockIdx.x] = iF + oF;
        }
    } else {
        g_offE1[o] = iE - vE + oE;
        g_offF1[o] = iF - vF + oF;
        if (tile == NTILES - 1) {
            g_totE1[t] = iE + oE;
            g_totF1[t] = iF + oF;
        }
    }
}

// ---------------- K5: per (t,n): smem binary search + combine + residual ---
__global__ void k_out(const float* __restrict__ x, float* __restrict__ out) {
    __shared__ float s_us[NN];       // 16 KB: sorted u for this block's t
    int warp = (blockIdx.x << 5) + (threadIdx.x >> 5);
    int lane = threadIdx.x & 31;
    const int t = warp >> 12;        // all warps in a block share t (128 blk/t)
    const int n = warp & (NN - 1);

    for (int i = threadIdx.x; i < NN; i += 1024)
        s_us[i] = g_us[t * NN + i];
    __syncthreads();

    const float c   = g_c[t * NN + n];
    const float thr = -c;
    int lo = 0, hi = NN;             // first index with us > thr
    while (lo < hi) {
        int mid = (lo + hi) >> 1;
        if (s_us[mid] <= thr) lo = mid + 1; else hi = mid;
    }
    const int k = lo;
    const float eC  = expf(c);
    const float eC2 = expf(0.01f * c);

    float4 te = *(const float4*)(g_totE + t * DD + lane * 4);
    float4 pe, pf;
    float pe1, pf1;
    if (k < NN) {
        const int tile = k >> 4;     // TILE_J = 16
        size_t ro = (size_t)(t * NN + k) * DD + lane * 4;
        size_t oo = (size_t)(t * NTILES + tile) * DD + lane * 4;
        float4 lE = *(const float4*)(g_preE + ro);
        float4 oE = *(const float4*)(g_offE + oo);
        float4 lF = *(const float4*)(g_preF + ro);
        float4 oF = *(const float4*)(g_offF + oo);
        pe = make_float4(lE.x + oE.x, lE.y + oE.y, lE.z + oE.z, lE.w + oE.w);
        pf = make_float4(lF.x + oF.x, lF.y + oF.y, lF.z + oF.z, lF.w + oF.w);
        pe1 = g_preE1[t * NN + k] + g_offE1[t * NTILES + tile];
        pf1 = g_preF1[t * NN + k] + g_offF1[t * NTILES + tile];
    } else {
        pe = te;
        pf = *(const float4*)(g_totF + t * DD + lane * 4);
        pe1 = g_totE1[t];
        pf1 = g_totF1[t];
    }
    const float denom = eC * (g_totE1[t] - pe1) + eC2 * pf1;
    const float inv = 1.0f / denom;

    float4 xv = *(const float4*)(x + (size_t)(n * TT + t) * DD + lane * 4);
    float4 o;
    {
        float num, agg, l;
        num = eC * (te.x - pe.x) + eC2 * pf.x; agg = num * inv;
        l = (agg >= 0.f) ? agg : 0.01f * agg;  o.x = xv.x - l;
        num = eC * (te.y - pe.y) + eC2 * pf.y; agg = num * inv;
        l = (agg >= 0.f) ? agg : 0.01f * agg;  o.y = xv.y - l;
        num = eC * (te.z - pe.z) + eC2 * pf.z; agg = num * inv;
        l = (agg >= 0.f) ? agg : 0.01f * agg;  o.z = xv.z - l;
        num = eC * (te.w - pe.w) + eC2 * pf.w; agg = num * inv;
        l = (agg >= 0.f) ? agg : 0.01f * agg;  o.w = xv.w - l;
    }
    *(float4*)(out + (size_t)(n * TT + t) * DD + lane * 4) = o;
}

// ---------------------------------------------------------------------------
extern "C" void kernel_launch(void* const* d_in, const int* in_sizes, int n_in,
                              void* d_out, int out_size) {
    const float* x  = (const float*)d_in[0];
    const float* W  = (const float*)d_in[1];
    const float* a1 = (const float*)d_in[2];
    const float* a2 = (const float*)d_in[3];
    float* out = (float*)d_out;

    k_gemm<<<NT / 128, 256>>>(x, W, a1, a2);
    k_sort<<<TT, 1024>>>();
    dim3 gp(NTILES, TT);
    k_prefix<<<gp, DD>>>();
    dim3 gs(DD + 1, TT);
    k_scan<<<gs, NTILES>>>();
    k_out<<<NT / 32, 1024>>>(x, out);
}

// round 5
// speedup vs baseline: 1.8944x; 1.1056x over previous
#include <cuda_runtime.h>
#include <math.h>

#define NN 4096
#define TT 4
#define DD 128
#define NT (NN*TT)           // 16384 rows
#define TILE_J 16
#define NTILES (NN/TILE_J)   // 256

// ---------------- scratch (device globals; no allocations) ----------------
__device__ float g_Wx[TT*NN*DD];        // Wx in [t][n][d] layout, 8 MB
__device__ float g_u[TT*NN];
__device__ float g_c[TT*NN];
__device__ float g_va1[DD];             // (W@a1)/16
__device__ float g_va2[DD];             // (W@a2)/16
__device__ unsigned g_key[TT*NN];       // sorted packed (qkey16<<16 | idx)
__device__ float g_wE[TT*NN];           // e^{u} in sorted order
__device__ float g_wF[TT*NN];           // e^{0.01 u} in sorted order
__device__ float g_tileE[TT*NTILES*DD];
__device__ float g_tileF[TT*NTILES*DD];
__device__ float g_tileE1[TT*NTILES];
__device__ float g_tileF1[TT*NTILES];
__device__ float g_offE[TT*NTILES*DD];
__device__ float g_offF[TT*NTILES*DD];
__device__ float g_offE1[TT*NTILES];
__device__ float g_offF1[TT*NTILES];
__device__ float g_totE[TT*DD];
__device__ float g_totF[TT*DD];
__device__ float g_totE1[TT];
__device__ float g_totF1[TT];
__device__ float g_preE[TT*NN*DD];      // TILE-LOCAL exclusive prefixes
__device__ float g_preF[TT*NN*DD];
__device__ float g_preE1[TT*NN];
__device__ float g_preF1[TT*NN];

// ---------------- f32x2 helpers (sm_100+) ----------------------------------
__device__ __forceinline__ unsigned long long pack2(float x, float y) {
    unsigned long long r;
    asm("mov.b64 %0, {%1, %2};" : "=l"(r) : "f"(x), "f"(y));
    return r;
}
__device__ __forceinline__ void unpack2(unsigned long long v, float& x, float& y) {
    asm("mov.b64 {%0, %1}, %2;" : "=f"(x), "=f"(y) : "l"(v));
}
__device__ __forceinline__ void ffma2(unsigned long long& acc,
                                      unsigned long long a, unsigned long long b) {
    asm("fma.rn.f32x2 %0, %1, %2, %0;" : "+l"(acc) : "l"(a), "l"(b));
}
__device__ __forceinline__ unsigned fmono(float f) {
    unsigned b = __float_as_uint(f);
    return (b & 0x80000000u) ? ~b : (b | 0x80000000u);
}

// ---------------- K0: va1 = (W@a1)/16, va2 = (W@a2)/16 ---------------------
__global__ void k_va(const float* __restrict__ W, const float* __restrict__ a1,
                     const float* __restrict__ a2) {
    __shared__ float as[2][DD];
    int tid = threadIdx.x;
    if (tid < DD) as[0][tid] = a1[tid];
    else          as[1][tid - DD] = a2[tid - DD];
    __syncthreads();
    int which = tid >> 7, k = tid & 127;
    const float* av = as[which];
    float s = 0.f;
#pragma unroll
    for (int j = 0; j < DD; j++) s += W[k * DD + j] * av[j];
    if (which) g_va2[k] = s * (1.0f / 16.0f);
    else       g_va1[k] = s * (1.0f / 16.0f);
}

// ---------------- K0b: u = x·va1, c = x·va2 (warp per row) -----------------
__global__ void k_uc(const float* __restrict__ x) {
    int warp = (blockIdx.x * blockDim.x + threadIdx.x) >> 5;
    int lane = threadIdx.x & 31;
    if (warp >= NT) return;
    float4 v  = *(const float4*)(x + (size_t)warp * DD + lane * 4);
    float4 w1 = *(const float4*)(g_va1 + lane * 4);
    float4 w2 = *(const float4*)(g_va2 + lane * 4);
    float s1 = v.x * w1.x + v.y * w1.y + v.z * w1.z + v.w * w1.w;
    float s2 = v.x * w2.x + v.y * w2.y + v.z * w2.z + v.w * w2.w;
#pragma unroll
    for (int o = 16; o > 0; o >>= 1) {
        s1 += __shfl_xor_sync(0xFFFFFFFFu, s1, o);
        s2 += __shfl_xor_sync(0xFFFFFFFFu, s2, o);
    }
    if (lane == 0) {
        int t = warp & 3, n = warp >> 2;   // x row r = n*T + t
        g_u[t * NN + n] = s1;
        g_c[t * NN + n] = s2;
    }
}

// ---------------- K1: Wx = x @ W via f32x2 (no epilogue) -------------------
__global__ void k_gemm(const float* __restrict__ x, const float* __restrict__ W) {
    __shared__ float Xs[32][132];   // [k][m], padded
    __shared__ float Ws[32][128];   // [k][j]
    const int tid = threadIdx.x;
    const int tx = tid & 15, ty = tid >> 4;
    const int row0 = blockIdx.x * 128;

    unsigned long long accp[8][4];
#pragma unroll
    for (int i = 0; i < 8; i++)
#pragma unroll
        for (int jp = 0; jp < 4; jp++) accp[i][jp] = 0ull;

    for (int k0 = 0; k0 < DD; k0 += 32) {
#pragma unroll
        for (int q = 0; q < 4; q++) {
            int m  = (tid >> 3) + q * 32;
            int kq = (tid & 7) * 4;
            float4 v = *(const float4*)(x + (size_t)(row0 + m) * DD + k0 + kq);
            Xs[kq + 0][m] = v.x; Xs[kq + 1][m] = v.y;
            Xs[kq + 2][m] = v.z; Xs[kq + 3][m] = v.w;
        }
#pragma unroll
        for (int q = 0; q < 4; q++) {
            int kk = (tid >> 5) + q * 8;
            int j4 = (tid & 31) * 4;
            *(float4*)&Ws[kk][j4] = *(const float4*)(W + (size_t)(k0 + kk) * DD + j4);
        }
        __syncthreads();
#pragma unroll
        for (int k = 0; k < 32; k++) {
            float a[8];
            float4 a0  = *(const float4*)&Xs[k][ty * 8];
            float4 a1v = *(const float4*)&Xs[k][ty * 8 + 4];
            a[0]=a0.x; a[1]=a0.y; a[2]=a0.z; a[3]=a0.w;
            a[4]=a1v.x; a[5]=a1v.y; a[6]=a1v.z; a[7]=a1v.w;
            unsigned long long b[4];
#pragma unroll
            for (int jp = 0; jp < 4; jp++)
                b[jp] = *(const unsigned long long*)&Ws[k][tx * 8 + jp * 2];
#pragma unroll
            for (int i = 0; i < 8; i++) {
                unsigned long long aa = pack2(a[i], a[i]);
#pragma unroll
                for (int jp = 0; jp < 4; jp++)
                    ffma2(accp[i][jp], aa, b[jp]);
            }
        }
        __syncthreads();
    }
#pragma unroll
    for (int i = 0; i < 8; i++) {
        float acc[8];
#pragma unroll
        for (int jp = 0; jp < 4; jp++)
            unpack2(accp[i][jp], acc[jp * 2], acc[jp * 2 + 1]);
        int r = row0 + ty * 8 + i;
        int t = r & 3;
        int n = r >> 2;
        float* o = g_Wx + ((size_t)(t * NN + n)) * DD + tx * 8;
        *(float4*)o       = make_float4(acc[0], acc[1], acc[2], acc[3]);
        *(float4*)(o + 4) = make_float4(acc[4], acc[5], acc[6], acc[7]);
    }
}

// ---------------- K2: u32 bitonic sort of (qkey|idx) per t -----------------
__global__ void k_sort() {
    __shared__ unsigned s[NN];
    const int t = blockIdx.x;
    for (int i = threadIdx.x; i < NN; i += blockDim.x)
        s[i] = (fmono(g_u[t * NN + i]) & 0xFFFF0000u) | (unsigned)i;
    __syncthreads();
    for (int k = 2; k <= NN; k <<= 1) {
        for (int j = k >> 1; j > 0; j >>= 1) {
#pragma unroll 4
            for (int i = threadIdx.x; i < NN; i += 1024) {
                int ixj = i ^ j;
                if (ixj > i) {
                    bool up = ((i & k) == 0);
                    unsigned a = s[i], b = s[ixj];
                    if ((a > b) == up) { s[i] = b; s[ixj] = a; }
                }
            }
            __syncthreads();
        }
    }
    for (int i = threadIdx.x; i < NN; i += blockDim.x) {
        unsigned v = s[i];
        g_key[t * NN + i] = v;
        float uu = g_u[t * NN + (v & 0xFFFFu)];
        g_wE[t * NN + i] = expf(uu);
        g_wF[t * NN + i] = expf(0.01f * uu);
    }
}

// ---------------- K3: tile-local prefixes + tile totals --------------------
__global__ void k_prefix() {
    __shared__ float swE[TILE_J], swF[TILE_J];
    __shared__ int   sp[TILE_J];
    const int t = blockIdx.y, tile = blockIdx.x, d = threadIdx.x;
    const int base = t * NN + tile * TILE_J;
    if (d < TILE_J) {
        swE[d] = g_wE[base + d];
        swF[d] = g_wF[base + d];
        sp[d]  = (int)(g_key[base + d] & 0xFFFFu);
    }
    __syncthreads();
    float rE = 0.f, rF = 0.f, rE1 = 0.f, rF1 = 0.f;
#pragma unroll
    for (int jj = 0; jj < TILE_J; jj++) {
        const int row = base + jj;
        g_preE[(size_t)row * DD + d] = rE;
        g_preF[(size_t)row * DD + d] = rF;
        if (d == 0) { g_preE1[row] = rE1; g_preF1[row] = rF1; }
        float v = g_Wx[((size_t)(t * NN + sp[jj])) * DD + d];
        rE += swE[jj] * v; rF += swF[jj] * v;
        rE1 += swE[jj];    rF1 += swF[jj];
    }
    const int o = t * NTILES + tile;
    g_tileE[(size_t)o * DD + d] = rE;
    g_tileF[(size_t)o * DD + d] = rF;
    if (d == 0) { g_tileE1[o] = rE1; g_tileF1[o] = rF1; }
}

// ---------------- K4: block-parallel scan of tile totals -------------------
__global__ void k_scan() {
    __shared__ float wsE[8], wsF[8];
    const unsigned FULL = 0xFFFFFFFFu;
    const int t = blockIdx.y;
    const int tile = threadIdx.x;
    const int lane = tile & 31, w = tile >> 5;

    float vE, vF;
    size_t o;
    if (blockIdx.x < DD) {
        const int d = blockIdx.x;
        o = (size_t)(t * NTILES + tile) * DD + d;
        vE = g_tileE[o]; vF = g_tileF[o];
    } else {
        o = (size_t)(t * NTILES + tile);
        vE = g_tileE1[o]; vF = g_tileF1[o];
    }
    float iE = vE, iF = vF;
#pragma unroll
    for (int off = 1; off < 32; off <<= 1) {
        float nE = __shfl_up_sync(FULL, iE, off);
        float nF = __shfl_up_sync(FULL, iF, off);
        if (lane >= off) { iE += nE; iF += nF; }
    }
    if (lane == 31) { wsE[w] = iE; wsF[w] = iF; }
    __syncthreads();
    float oE = 0.f, oF = 0.f;
#pragma unroll
    for (int q = 0; q < 8; q++)
        if (q < w) { oE += wsE[q]; oF += wsF[q]; }
    if (blockIdx.x < DD) {
        g_offE[o] = iE - vE + oE;
        g_offF[o] = iF - vF + oF;
        if (tile == NTILES - 1) {
            g_totE[t * DD + blockIdx.x] = iE + oE;
            g_totF[t * DD + blockIdx.x] = iF + oF;
        }
    } else {
        g_offE1[o] = iE - vE + oE;
        g_offF1[o] = iF - vF + oF;
        if (tile == NTILES - 1) {
            g_totE1[t] = iE + oE;
            g_totF1[t] = iF + oF;
        }
    }
}

// ---------------- K5: per (t,n): smem binary search + combine --------------
__global__ void k_out(const float* __restrict__ x, float* __restrict__ out) {
    __shared__ unsigned s_key[NN];   // 16 KB sorted keys for this block's t
    int warp = (blockIdx.x << 5) + (threadIdx.x >> 5);
    int lane = threadIdx.x & 31;
    const int t = warp >> 12;        // 128 blocks per t
    const int n = warp & (NN - 1);

    for (int i = threadIdx.x; i < NN; i += 1024)
        s_key[i] = g_key[t * NN + i];
    __syncthreads();

    const float c = g_c[t * NN + n];
    const unsigned qthr = (fmono(-c) & 0xFFFF0000u) | 0xFFFFu;
    int lo = 0, hi = NN;             // first index with key > qthr
    while (lo < hi) {
        int mid = (lo + hi) >> 1;
        if (s_key[mid] <= qthr) lo = mid + 1; else hi = mid;
    }
    const int k = lo;
    const float eC  = expf(c);
    const float eC2 = expf(0.01f * c);

    float4 te = *(const float4*)(g_totE + t * DD + lane * 4);
    float4 pe, pf;
    float pe1, pf1;
    if (k < NN) {
        const int tile = k >> 4;     // TILE_J = 16
        size_t ro = (size_t)(t * NN + k) * DD + lane * 4;
        size_t oo = (size_t)(t * NTILES + tile) * DD + lane * 4;
        float4 lE = *(const float4*)(g_preE + ro);
        float4 oE = *(const float4*)(g_offE + oo);
        float4 lF = *(const float4*)(g_preF + ro);
        float4 oF = *(const float4*)(g_offF + oo);
        pe = make_float4(lE.x + oE.x, lE.y + oE.y, lE.z + oE.z, lE.w + oE.w);
        pf = make_float4(lF.x + oF.x, lF.y + oF.y, lF.z + oF.z, lF.w + oF.w);
        pe1 = g_preE1[t * NN + k] + g_offE1[t * NTILES + tile];
        pf1 = g_preF1[t * NN + k] + g_offF1[t * NTILES + tile];
    } else {
        pe = te;
        pf = *(const float4*)(g_totF + t * DD + lane * 4);
        pe1 = g_totE1[t];
        pf1 = g_totF1[t];
    }
    const float denom = eC * (g_totE1[t] - pe1) + eC2 * pf1;
    const float inv = 1.0f / denom;

    float4 xv = *(const float4*)(x + (size_t)(n * TT + t) * DD + lane * 4);
    float4 o;
    {
        float num, agg, l;
        num = eC * (te.x - pe.x) + eC2 * pf.x; agg = num * inv;
        l = (agg >= 0.f) ? agg : 0.01f * agg;  o.x = xv.x - l;
        num = eC * (te.y - pe.y) + eC2 * pf.y; agg = num * inv;
        l = (agg >= 0.f) ? agg : 0.01f * agg;  o.y = xv.y - l;
        num = eC * (te.z - pe.z) + eC2 * pf.z; agg = num * inv;
        l = (agg >= 0.f) ? agg : 0.01f * agg;  o.z = xv.z - l;
        num = eC * (te.w - pe.w) + eC2 * pf.w; agg = num * inv;
        l = (agg >= 0.f) ? agg : 0.01f * agg;  o.w = xv.w - l;
    }
    *(float4*)(out + (size_t)(n * TT + t) * DD + lane * 4) = o;
}

// ---------------------------------------------------------------------------
extern "C" void kernel_launch(void* const* d_in, const int* in_sizes, int n_in,
                              void* d_out, int out_size) {
    const float* x  = (const float*)d_in[0];
    const float* W  = (const float*)d_in[1];
    const float* a1 = (const float*)d_in[2];
    const float* a2 = (const float*)d_in[3];
    float* out = (float*)d_out;

    static cudaStream_t s2 = nullptr;
    static cudaEvent_t ev1 = nullptr, ev2 = nullptr;
    if (!s2) {
        cudaStreamCreateWithFlags(&s2, cudaStreamNonBlocking);
        cudaEventCreateWithFlags(&ev1, cudaEventDisableTiming);
        cudaEventCreateWithFlags(&ev2, cudaEventDisableTiming);
    }

    k_va<<<1, 256>>>(W, a1, a2);
    k_uc<<<NT / 8, 256>>>(x);
    // fork: sort (4 SMs, long) runs concurrently with the main GEMM
    cudaEventRecord(ev1, 0);
    cudaStreamWaitEvent(s2, ev1, 0);
    k_sort<<<TT, 1024, 0, s2>>>();
    cudaEventRecord(ev2, s2);
    k_gemm<<<NT / 128, 256>>>(x, W);
    cudaStreamWaitEvent(0, ev2, 0);
    // join: prefix needs both Wx and sorted keys/weights
    dim3 gp(NTILES, TT);
    k_prefix<<<gp, DD>>>();
    dim3 gs(DD + 1, TT);
    k_scan<<<gs, NTILES>>>();
    k_out<<<NT / 32, 1024>>>(x, out);
}